// round 7
// baseline (speedup 1.0000x reference)
#include <cuda_runtime.h>
#include <math_constants.h>

#define D        256
#define NBLK     592          // flash grid: 4 CTAs per SM
#define THREADS  256
#define WARPS    (THREADS / 32)
#define NW       (NBLK * WARPS)     // 4736 warps
#define NSLOTS   100000
#define RBLK     512
#define RGRID    256

// ---- device scratch (no allocations allowed) ----
__device__ __align__(16) float g_u0[D];
__device__ __align__(16) float g_v[D];
__device__ __align__(16) float g_m[D];
__device__ __align__(16) float g_msum[D];
__device__ __align__(16) float g_G[D * D];
__device__ float g_pmax[NBLK];
__device__ float g_psum[NBLK];
__device__ __align__(16) float g_pacc[D * NBLK];   // [dim][cta]
__device__ unsigned g_cnt;   // zero-init; always returns to 0
__device__ unsigned g_gen;   // monotonically increasing across replays (ok)

__device__ __forceinline__ float warp_sum(float d) {
#pragma unroll
    for (int m = 16; m >= 1; m >>= 1) d += __shfl_xor_sync(0xffffffffu, d, m);
    return d;
}
__device__ __forceinline__ float warp_max(float d) {
#pragma unroll
    for (int m = 16; m >= 1; m >>= 1) d = fmaxf(d, __shfl_xor_sync(0xffffffffu, d, m));
    return d;
}

// 32B L2-persistent load (sm_103 needs v8.b32 width with .L2::evict_last)
__device__ __forceinline__ void ldg_el8(const void* p, float4& a, float4& b) {
    unsigned r0, r1, r2, r3, r4, r5, r6, r7;
    asm("ld.global.nc.L2::evict_last.v8.b32 {%0,%1,%2,%3,%4,%5,%6,%7}, [%8];"
        : "=r"(r0), "=r"(r1), "=r"(r2), "=r"(r3),
          "=r"(r4), "=r"(r5), "=r"(r6), "=r"(r7) : "l"(p));
    a.x = __uint_as_float(r0); a.y = __uint_as_float(r1);
    a.z = __uint_as_float(r2); a.w = __uint_as_float(r3);
    b.x = __uint_as_float(r4); b.y = __uint_as_float(r5);
    b.z = __uint_as_float(r6); b.w = __uint_as_float(r7);
}

// ---- setup: blocks 0..255 compute G = A^T C ; block 256 computes u0, v0 ----
__global__ void __launch_bounds__(256, 4)
setup_kernel(const float* __restrict__ A, const float* __restrict__ B,
             const float* __restrict__ C, const float* __restrict__ q) {
    const int t = threadIdx.x;
    if (blockIdx.x < 256) {
        __shared__ float colA[D];
        const int k = blockIdx.x;
        colA[t] = A[t * D + k];          // column k of A
        __syncthreads();
        float acc = 0.f;
#pragma unroll 8
        for (int dd = 0; dd < D; dd++)
            acc = fmaf(colA[dd], C[dd * D + t], acc);
        g_G[k * D + t] = acc;            // G[k][t] = sum_d A[d][k] C[d][t]
    } else {
        __shared__ float qs[D];
        __shared__ float us[D];
        const int warp = t >> 5, lane = t & 31;
        qs[t] = q[t];
        __syncthreads();
        for (int row = warp; row < D; row += 8) {
            const float4* r = reinterpret_cast<const float4*>(B + row * D);
            float4 c0 = r[lane * 2], c1 = r[lane * 2 + 1];
            float d = c0.x * qs[lane * 8 + 0] + c0.y * qs[lane * 8 + 1]
                    + c0.z * qs[lane * 8 + 2] + c0.w * qs[lane * 8 + 3]
                    + c1.x * qs[lane * 8 + 4] + c1.y * qs[lane * 8 + 5]
                    + c1.z * qs[lane * 8 + 6] + c1.w * qs[lane * 8 + 7];
            d = warp_sum(d);
            if (lane == 0) { us[row] = d; g_u0[row] = d; }
        }
        __syncthreads();
        float v = 0.f;
#pragma unroll 8
        for (int j = 0; j < D; j++) v = fmaf(A[j * D + t], us[j], v);
        g_v[t] = v;
    }
}

// ---------------- flash pass: fused score+softmax+weighted-sum ------------
__global__ void __launch_bounds__(THREADS, 4)
flash_kernel(const float* __restrict__ memory) {
    const int lane = threadIdx.x & 31;
    const int warp = threadIdx.x >> 5;
    const int gw   = blockIdx.x * WARPS + warp;

    float4 v0 = *reinterpret_cast<const float4*>(g_v + lane * 8);
    float4 v1 = *reinterpret_cast<const float4*>(g_v + lane * 8 + 4);

    float mx = -CUDART_INF_F, sm = 0.f;
    float acc[8];
#pragma unroll
    for (int i = 0; i < 8; i++) acc[i] = 0.f;

    const char* base = reinterpret_cast<const char*>(memory);
    const int loff = lane * 32;
    int s0 = gw;
    while (s0 + NW < NSLOTS) {
        const void* r1 = base + (size_t)s0 * 1024 + loff;
        const void* r2 = base + (size_t)(s0 + NW) * 1024 + loff;
        float4 a1, b1, a2, b2;
        ldg_el8(r1, a1, b1);
        ldg_el8(r2, a2, b2);

        float d1 = a1.x * v0.x;     float d2 = a2.x * v0.x;
        d1 = fmaf(a1.y, v0.y, d1);  d2 = fmaf(a2.y, v0.y, d2);
        d1 = fmaf(a1.z, v0.z, d1);  d2 = fmaf(a2.z, v0.z, d2);
        d1 = fmaf(a1.w, v0.w, d1);  d2 = fmaf(a2.w, v0.w, d2);
        d1 = fmaf(b1.x, v1.x, d1);  d2 = fmaf(b2.x, v1.x, d2);
        d1 = fmaf(b1.y, v1.y, d1);  d2 = fmaf(b2.y, v1.y, d2);
        d1 = fmaf(b1.z, v1.z, d1);  d2 = fmaf(b2.z, v1.z, d2);
        d1 = fmaf(b1.w, v1.w, d1);  d2 = fmaf(b2.w, v1.w, d2);
#pragma unroll
        for (int m = 16; m >= 1; m >>= 1) {
            d1 += __shfl_xor_sync(0xffffffffu, d1, m);
            d2 += __shfl_xor_sync(0xffffffffu, d2, m);
        }
        float dmax = fmaxf(d1, d2);
        if (dmax > mx) {                       // warp-uniform branch
            float scale = __expf(mx - dmax);
            mx = dmax; sm *= scale;
#pragma unroll
            for (int i = 0; i < 8; i++) acc[i] *= scale;
        }
        float w1 = __expf(d1 - mx);
        float w2 = __expf(d2 - mx);
        sm += w1 + w2;
        acc[0] = fmaf(w1, a1.x, fmaf(w2, a2.x, acc[0]));
        acc[1] = fmaf(w1, a1.y, fmaf(w2, a2.y, acc[1]));
        acc[2] = fmaf(w1, a1.z, fmaf(w2, a2.z, acc[2]));
        acc[3] = fmaf(w1, a1.w, fmaf(w2, a2.w, acc[3]));
        acc[4] = fmaf(w1, b1.x, fmaf(w2, b2.x, acc[4]));
        acc[5] = fmaf(w1, b1.y, fmaf(w2, b2.y, acc[5]));
        acc[6] = fmaf(w1, b1.z, fmaf(w2, b2.z, acc[6]));
        acc[7] = fmaf(w1, b1.w, fmaf(w2, b2.w, acc[7]));
        s0 += 2 * NW;
    }
    if (s0 < NSLOTS) {
        const void* r1 = base + (size_t)s0 * 1024 + loff;
        float4 a1, b1;
        ldg_el8(r1, a1, b1);
        float d = a1.x * v0.x;
        d = fmaf(a1.y, v0.y, d); d = fmaf(a1.z, v0.z, d); d = fmaf(a1.w, v0.w, d);
        d = fmaf(b1.x, v1.x, d); d = fmaf(b1.y, v1.y, d);
        d = fmaf(b1.z, v1.z, d); d = fmaf(b1.w, v1.w, d);
        d = warp_sum(d);
        if (d > mx) {
            float scale = __expf(mx - d);
            mx = d; sm *= scale;
#pragma unroll
            for (int i = 0; i < 8; i++) acc[i] *= scale;
        }
        float w = __expf(d - mx);
        sm += w;
        acc[0] = fmaf(w, a1.x, acc[0]); acc[1] = fmaf(w, a1.y, acc[1]);
        acc[2] = fmaf(w, a1.z, acc[2]); acc[3] = fmaf(w, a1.w, acc[3]);
        acc[4] = fmaf(w, b1.x, acc[4]); acc[5] = fmaf(w, b1.y, acc[5]);
        acc[6] = fmaf(w, b1.z, acc[6]); acc[7] = fmaf(w, b1.w, acc[7]);
    }

    __shared__ float s_mx[WARPS], s_sm[WARPS];
    __shared__ float s_acc[WARPS][D];
    if (lane == 0) { s_mx[warp] = mx; s_sm[warp] = sm; }
#pragma unroll
    for (int i = 0; i < 8; i++) s_acc[warp][lane * 8 + i] = acc[i];
    __syncthreads();

    const int t = threadIdx.x;
    float M = s_mx[0];
#pragma unroll
    for (int w = 1; w < WARPS; w++) M = fmaxf(M, s_mx[w]);
    float tot = 0.f;
#pragma unroll
    for (int w = 0; w < WARPS; w++) tot = fmaf(s_acc[w][t], __expf(s_mx[w] - M), tot);
    g_pacc[t * NBLK + blockIdx.x] = tot;       // transposed for reduce
    if (t == 0) {
        float S = 0.f;
#pragma unroll
        for (int w = 0; w < WARPS; w++) S = fmaf(s_sm[w], __expf(s_mx[w] - M), S);
        g_psum[blockIdx.x] = S;
        g_pmax[blockIdx.x] = M;
    }
}

// ------- fused reduce: CTA j -> m[j], grid barrier, then v/out update ------
__global__ void __launch_bounds__(RBLK, 2)
reduce_fused(int hop, const float* __restrict__ C, float* __restrict__ out) {
    __shared__ float s1[16], s2[16];
    __shared__ float sM;
    const int j = blockIdx.x, t = threadIdx.x;
    const int warp = t >> 5, lane = t & 31;

    // ---- phase A: m[j] from flash partials ----
    const bool v0ok = (t < NBLK), v1ok = (t + RBLK < NBLK);
    float pm0 = v0ok ? g_pmax[t] : -CUDART_INF_F;
    float pm1 = v1ok ? g_pmax[t + RBLK] : -CUDART_INF_F;
    float ps0 = v0ok ? g_psum[t] : 0.f;
    float ps1 = v1ok ? g_psum[t + RBLK] : 0.f;
    float pa0 = v0ok ? g_pacc[j * NBLK + t] : 0.f;
    float pa1 = v1ok ? g_pacc[j * NBLK + t + RBLK] : 0.f;

    float mx = warp_max(fmaxf(pm0, pm1));
    if (lane == 0) s1[warp] = mx;
    __syncthreads();
    if (warp == 0) {
        float v = (lane < 16) ? s1[lane] : -CUDART_INF_F;
        v = warp_max(v);
        if (lane == 0) sM = v;
    }
    __syncthreads();
    const float M = sM;

    float w0 = v0ok ? __expf(pm0 - M) : 0.f;
    float w1 = v1ok ? __expf(pm1 - M) : 0.f;
    float ss = fmaf(w0, ps0, w1 * ps1);
    float pa = fmaf(w0, pa0, w1 * pa1);
#pragma unroll
    for (int m = 16; m >= 1; m >>= 1) {
        ss += __shfl_xor_sync(0xffffffffu, ss, m);
        pa += __shfl_xor_sync(0xffffffffu, pa, m);
    }
    if (lane == 0) { s1[warp] = ss; s2[warp] = pa; }
    __syncthreads();
    if (warp == 0) {
        float a = (lane < 16) ? s1[lane] : 0.f;
        float b = (lane < 16) ? s2[lane] : 0.f;
#pragma unroll
        for (int m = 16; m >= 1; m >>= 1) {
            a += __shfl_xor_sync(0xffffffffu, a, m);
            b += __shfl_xor_sync(0xffffffffu, b, m);
        }
        if (lane == 0) {
            float mj = b / a;
            g_m[j] = mj;
            g_msum[j] = (hop == 0) ? mj : g_msum[j] + mj;
        }
    }

    // ---- grid barrier over 256 CTAs (all co-resident: 512thr x 2/SM) ----
    __syncthreads();
    if (t == 0) {
        unsigned gen = *((volatile unsigned*)&g_gen);
        __threadfence();
        if (atomicAdd(&g_cnt, 1u) == RGRID - 1) {
            g_cnt = 0;
            __threadfence();
            atomicAdd(&g_gen, 1u);
        } else {
            while (*((volatile unsigned*)&g_gen) == gen) { }
        }
        __threadfence();
    }
    __syncthreads();

    // ---- phase C: CTA j -> v[j] += G[j,:].m   /   out[j] = u0[j]+C[j,:].msum
    float p;
    if (hop < 2) {
        p = (t < D) ? __ldcg(&g_G[j * D + t]) * __ldcg(&g_m[t]) : 0.f;
    } else {
        p = (t < D) ? C[j * D + t] * __ldcg(&g_msum[t]) : 0.f;
    }
    p = warp_sum(p);
    if (lane == 0) s1[warp] = p;
    __syncthreads();
    if (warp == 0) {
        float a = (lane < 16) ? s1[lane] : 0.f;
        a = warp_sum(a);
        if (lane == 0) {
            if (hop < 2) g_v[j] += a;
            else         out[j] = g_u0[j] + a;
        }
    }
}

extern "C" void kernel_launch(void* const* d_in, const int* in_sizes, int n_in,
                              void* d_out, int out_size) {
    const float* memory = (const float*)d_in[0];
    const float* query  = (const float*)d_in[1];
    const float* A      = (const float*)d_in[2];
    const float* B      = (const float*)d_in[3];
    const float* C      = (const float*)d_in[4];
    float* out = (float*)d_out;

    setup_kernel<<<257, 256>>>(A, B, C, query);
    for (int h = 0; h < 3; h++) {
        flash_kernel<<<NBLK, THREADS>>>(memory);
        reduce_fused<<<RGRID, RBLK>>>(h, C, out);
    }
}

// round 8
// speedup vs baseline: 1.1688x; 1.1688x over previous
#include <cuda_runtime.h>
#include <math_constants.h>

#define D        256
#define NBLK     592          // flash grid: 4 CTAs per SM
#define THREADS  256
#define WARPS    (THREADS / 32)
#define NW       (NBLK * WARPS)     // 4736 warps
#define NSLOTS   100000
#define RBLK     512
#define SPLIT    65536        // slots [0,SPLIT): pin in L2; rest: stream

// ---- device scratch (no allocations allowed) ----
__device__ __align__(16) float g_u0[D];
__device__ __align__(16) float g_v[D];
__device__ __align__(16) float g_m[D];
__device__ __align__(16) float g_msum[D];
__device__ __align__(16) float g_G[D * D];
__device__ float g_pmax[NBLK];
__device__ float g_psum[NBLK];
__device__ __align__(16) float g_pacc[D * NBLK];   // [dim][cta]

__device__ __forceinline__ float warp_sum(float d) {
#pragma unroll
    for (int m = 16; m >= 1; m >>= 1) d += __shfl_xor_sync(0xffffffffu, d, m);
    return d;
}
__device__ __forceinline__ float warp_max(float d) {
#pragma unroll
    for (int m = 16; m >= 1; m >>= 1) d = fmaxf(d, __shfl_xor_sync(0xffffffffu, d, m));
    return d;
}

// 32B loads, L2 policy variants (sm_103: evict hints require v8.b32 width)
__device__ __forceinline__ void ldg_last8(const void* p, float4& a, float4& b) {
    unsigned r0, r1, r2, r3, r4, r5, r6, r7;
    asm("ld.global.nc.L2::evict_last.v8.b32 {%0,%1,%2,%3,%4,%5,%6,%7}, [%8];"
        : "=r"(r0), "=r"(r1), "=r"(r2), "=r"(r3),
          "=r"(r4), "=r"(r5), "=r"(r6), "=r"(r7) : "l"(p));
    a.x = __uint_as_float(r0); a.y = __uint_as_float(r1);
    a.z = __uint_as_float(r2); a.w = __uint_as_float(r3);
    b.x = __uint_as_float(r4); b.y = __uint_as_float(r5);
    b.z = __uint_as_float(r6); b.w = __uint_as_float(r7);
}
__device__ __forceinline__ void ldg_first8(const void* p, float4& a, float4& b) {
    unsigned r0, r1, r2, r3, r4, r5, r6, r7;
    asm("ld.global.nc.L2::evict_first.v8.b32 {%0,%1,%2,%3,%4,%5,%6,%7}, [%8];"
        : "=r"(r0), "=r"(r1), "=r"(r2), "=r"(r3),
          "=r"(r4), "=r"(r5), "=r"(r6), "=r"(r7) : "l"(p));
    a.x = __uint_as_float(r0); a.y = __uint_as_float(r1);
    a.z = __uint_as_float(r2); a.w = __uint_as_float(r3);
    b.x = __uint_as_float(r4); b.y = __uint_as_float(r5);
    b.z = __uint_as_float(r6); b.w = __uint_as_float(r7);
}
// slot index is warp-uniform -> branch is free
__device__ __forceinline__ void load_slot(const char* base, int slot, int loff,
                                          float4& a, float4& b) {
    const void* p = base + (size_t)slot * 1024 + loff;
    if (slot < SPLIT) ldg_last8(p, a, b);
    else              ldg_first8(p, a, b);
}

// ---- setup: blocks 0..255 compute G = A^T C ; block 256 computes u0, v0 ----
__global__ void __launch_bounds__(256, 4)
setup_kernel(const float* __restrict__ A, const float* __restrict__ B,
             const float* __restrict__ C, const float* __restrict__ q) {
    const int t = threadIdx.x;
    if (blockIdx.x < 256) {
        __shared__ float colA[D];
        const int k = blockIdx.x;
        colA[t] = A[t * D + k];          // column k of A
        __syncthreads();
        float acc = 0.f;
#pragma unroll 8
        for (int dd = 0; dd < D; dd++)
            acc = fmaf(colA[dd], C[dd * D + t], acc);
        g_G[k * D + t] = acc;            // G[k][t] = sum_d A[d][k] C[d][t]
    } else {
        __shared__ float qs[D];
        __shared__ float us[D];
        const int warp = t >> 5, lane = t & 31;
        qs[t] = q[t];
        __syncthreads();
        for (int row = warp; row < D; row += 8) {
            const float4* r = reinterpret_cast<const float4*>(B + row * D);
            float4 c0 = r[lane * 2], c1 = r[lane * 2 + 1];
            float d = c0.x * qs[lane * 8 + 0] + c0.y * qs[lane * 8 + 1]
                    + c0.z * qs[lane * 8 + 2] + c0.w * qs[lane * 8 + 3]
                    + c1.x * qs[lane * 8 + 4] + c1.y * qs[lane * 8 + 5]
                    + c1.z * qs[lane * 8 + 6] + c1.w * qs[lane * 8 + 7];
            d = warp_sum(d);
            if (lane == 0) { us[row] = d; g_u0[row] = d; }
        }
        __syncthreads();
        float v = 0.f;
#pragma unroll 8
        for (int j = 0; j < D; j++) v = fmaf(A[j * D + t], us[j], v);
        g_v[t] = v;
    }
}

// ---------------- flash pass: fused score+softmax+weighted-sum ------------
__global__ void __launch_bounds__(THREADS, 4)
flash_kernel(const float* __restrict__ memory) {
    const int lane = threadIdx.x & 31;
    const int warp = threadIdx.x >> 5;
    const int gw   = blockIdx.x * WARPS + warp;

    float4 v0 = *reinterpret_cast<const float4*>(g_v + lane * 8);
    float4 v1 = *reinterpret_cast<const float4*>(g_v + lane * 8 + 4);

    float mx = -CUDART_INF_F, sm = 0.f;
    float acc[8];
#pragma unroll
    for (int i = 0; i < 8; i++) acc[i] = 0.f;

    const char* base = reinterpret_cast<const char*>(memory);
    const int loff = lane * 32;
    int s0 = gw;
    while (s0 + NW < NSLOTS) {
        float4 a1, b1, a2, b2;
        load_slot(base, s0, loff, a1, b1);
        load_slot(base, s0 + NW, loff, a2, b2);

        float d1 = a1.x * v0.x;     float d2 = a2.x * v0.x;
        d1 = fmaf(a1.y, v0.y, d1);  d2 = fmaf(a2.y, v0.y, d2);
        d1 = fmaf(a1.z, v0.z, d1);  d2 = fmaf(a2.z, v0.z, d2);
        d1 = fmaf(a1.w, v0.w, d1);  d2 = fmaf(a2.w, v0.w, d2);
        d1 = fmaf(b1.x, v1.x, d1);  d2 = fmaf(b2.x, v1.x, d2);
        d1 = fmaf(b1.y, v1.y, d1);  d2 = fmaf(b2.y, v1.y, d2);
        d1 = fmaf(b1.z, v1.z, d1);  d2 = fmaf(b2.z, v1.z, d2);
        d1 = fmaf(b1.w, v1.w, d1);  d2 = fmaf(b2.w, v1.w, d2);
#pragma unroll
        for (int m = 16; m >= 1; m >>= 1) {
            d1 += __shfl_xor_sync(0xffffffffu, d1, m);
            d2 += __shfl_xor_sync(0xffffffffu, d2, m);
        }
        float dmax = fmaxf(d1, d2);
        if (dmax > mx) {                       // warp-uniform branch
            float scale = __expf(mx - dmax);
            mx = dmax; sm *= scale;
#pragma unroll
            for (int i = 0; i < 8; i++) acc[i] *= scale;
        }
        float w1 = __expf(d1 - mx);
        float w2 = __expf(d2 - mx);
        sm += w1 + w2;
        acc[0] = fmaf(w1, a1.x, fmaf(w2, a2.x, acc[0]));
        acc[1] = fmaf(w1, a1.y, fmaf(w2, a2.y, acc[1]));
        acc[2] = fmaf(w1, a1.z, fmaf(w2, a2.z, acc[2]));
        acc[3] = fmaf(w1, a1.w, fmaf(w2, a2.w, acc[3]));
        acc[4] = fmaf(w1, b1.x, fmaf(w2, b2.x, acc[4]));
        acc[5] = fmaf(w1, b1.y, fmaf(w2, b2.y, acc[5]));
        acc[6] = fmaf(w1, b1.z, fmaf(w2, b2.z, acc[6]));
        acc[7] = fmaf(w1, b1.w, fmaf(w2, b2.w, acc[7]));
        s0 += 2 * NW;
    }
    if (s0 < NSLOTS) {
        float4 a1, b1;
        load_slot(base, s0, loff, a1, b1);
        float d = a1.x * v0.x;
        d = fmaf(a1.y, v0.y, d); d = fmaf(a1.z, v0.z, d); d = fmaf(a1.w, v0.w, d);
        d = fmaf(b1.x, v1.x, d); d = fmaf(b1.y, v1.y, d);
        d = fmaf(b1.z, v1.z, d); d = fmaf(b1.w, v1.w, d);
        d = warp_sum(d);
        if (d > mx) {
            float scale = __expf(mx - d);
            mx = d; sm *= scale;
#pragma unroll
            for (int i = 0; i < 8; i++) acc[i] *= scale;
        }
        float w = __expf(d - mx);
        sm += w;
        acc[0] = fmaf(w, a1.x, acc[0]); acc[1] = fmaf(w, a1.y, acc[1]);
        acc[2] = fmaf(w, a1.z, acc[2]); acc[3] = fmaf(w, a1.w, acc[3]);
        acc[4] = fmaf(w, b1.x, acc[4]); acc[5] = fmaf(w, b1.y, acc[5]);
        acc[6] = fmaf(w, b1.z, acc[6]); acc[7] = fmaf(w, b1.w, acc[7]);
    }

    __shared__ float s_mx[WARPS], s_sm[WARPS];
    __shared__ float s_acc[WARPS][D];
    if (lane == 0) { s_mx[warp] = mx; s_sm[warp] = sm; }
#pragma unroll
    for (int i = 0; i < 8; i++) s_acc[warp][lane * 8 + i] = acc[i];
    __syncthreads();

    const int t = threadIdx.x;
    float M = s_mx[0];
#pragma unroll
    for (int w = 1; w < WARPS; w++) M = fmaxf(M, s_mx[w]);
    float tot = 0.f;
#pragma unroll
    for (int w = 0; w < WARPS; w++) tot = fmaf(s_acc[w][t], __expf(s_mx[w] - M), tot);
    g_pacc[t * NBLK + blockIdx.x] = tot;       // transposed for reduce
    if (t == 0) {
        float S = 0.f;
#pragma unroll
        for (int w = 0; w < WARPS; w++) S = fmaf(s_sm[w], __expf(s_mx[w] - M), S);
        g_psum[blockIdx.x] = S;
        g_pmax[blockIdx.x] = M;
    }
}

// ---------------- distributed reduce: CTA j -> m[j]  (shfl-based) ---------
__global__ void __launch_bounds__(RBLK, 2)
reduce_kernel(int hop) {
    __shared__ float s1[16], s2[16];
    __shared__ float sM;
    const int j = blockIdx.x, t = threadIdx.x;
    const int warp = t >> 5, lane = t & 31;

    const bool v0ok = (t < NBLK), v1ok = (t + RBLK < NBLK);
    float pm0 = v0ok ? g_pmax[t] : -CUDART_INF_F;
    float pm1 = v1ok ? g_pmax[t + RBLK] : -CUDART_INF_F;
    float ps0 = v0ok ? g_psum[t] : 0.f;
    float ps1 = v1ok ? g_psum[t + RBLK] : 0.f;
    float pa0 = v0ok ? g_pacc[j * NBLK + t] : 0.f;
    float pa1 = v1ok ? g_pacc[j * NBLK + t + RBLK] : 0.f;

    float mx = warp_max(fmaxf(pm0, pm1));
    if (lane == 0) s1[warp] = mx;
    __syncthreads();
    if (warp == 0) {
        float v = (lane < 16) ? s1[lane] : -CUDART_INF_F;
        v = warp_max(v);
        if (lane == 0) sM = v;
    }
    __syncthreads();
    const float M = sM;

    float w0 = v0ok ? __expf(pm0 - M) : 0.f;
    float w1 = v1ok ? __expf(pm1 - M) : 0.f;
    float ss = fmaf(w0, ps0, w1 * ps1);
    float pa = fmaf(w0, pa0, w1 * pa1);
#pragma unroll
    for (int m = 16; m >= 1; m >>= 1) {
        ss += __shfl_xor_sync(0xffffffffu, ss, m);
        pa += __shfl_xor_sync(0xffffffffu, pa, m);
    }
    if (lane == 0) { s1[warp] = ss; s2[warp] = pa; }
    __syncthreads();
    if (warp == 0) {
        float a = (lane < 16) ? s1[lane] : 0.f;
        float b = (lane < 16) ? s2[lane] : 0.f;
#pragma unroll
        for (int m = 16; m >= 1; m >>= 1) {
            a += __shfl_xor_sync(0xffffffffu, a, m);
            b += __shfl_xor_sync(0xffffffffu, b, m);
        }
        if (lane == 0) {
            float mj = b / a;
            g_m[j] = mj;
            g_msum[j] = (hop == 0) ? mj : g_msum[j] + mj;
        }
    }
}

// ---------------- v += G m   (warp per row) --------------------------------
__global__ void __launch_bounds__(RBLK, 2)
vupd_kernel() {
    const int t = threadIdx.x, warp = t >> 5, lane = t & 31;
    const int row = blockIdx.x * (RBLK / 32) + warp;
    const float4* r  = reinterpret_cast<const float4*>(g_G + row * D) + lane * 2;
    const float4* mm = reinterpret_cast<const float4*>(g_m) + lane * 2;
    float4 c0 = r[0], c1 = r[1];
    float4 m0 = mm[0], m1 = mm[1];
    float d = c0.x * m0.x + c0.y * m0.y + c0.z * m0.z + c0.w * m0.w
            + c1.x * m1.x + c1.y * m1.y + c1.z * m1.z + c1.w * m1.w;
    d = warp_sum(d);
    if (lane == 0) g_v[row] += d;
}

// ---------------- out = u0 + C msum  (warp per row) ------------------------
__global__ void __launch_bounds__(RBLK, 2)
final_kernel(const float* __restrict__ C, float* __restrict__ out) {
    const int t = threadIdx.x, warp = t >> 5, lane = t & 31;
    const int row = blockIdx.x * (RBLK / 32) + warp;
    const float4* r  = reinterpret_cast<const float4*>(C + row * D) + lane * 2;
    const float4* mm = reinterpret_cast<const float4*>(g_msum) + lane * 2;
    float4 c0 = r[0], c1 = r[1];
    float4 m0 = mm[0], m1 = mm[1];
    float d = c0.x * m0.x + c0.y * m0.y + c0.z * m0.z + c0.w * m0.w
            + c1.x * m1.x + c1.y * m1.y + c1.z * m1.z + c1.w * m1.w;
    d = warp_sum(d);
    if (lane == 0) out[row] = g_u0[row] + d;
}

extern "C" void kernel_launch(void* const* d_in, const int* in_sizes, int n_in,
                              void* d_out, int out_size) {
    const float* memory = (const float*)d_in[0];
    const float* query  = (const float*)d_in[1];
    const float* A      = (const float*)d_in[2];
    const float* B      = (const float*)d_in[3];
    const float* C      = (const float*)d_in[4];
    float* out = (float*)d_out;

    setup_kernel<<<257, 256>>>(A, B, C, query);
    for (int h = 0; h < 3; h++) {
        flash_kernel<<<NBLK, THREADS>>>(memory);
        reduce_kernel<<<256, RBLK>>>(h);
        if (h < 2) vupd_kernel<<<16, RBLK>>>();
        else       final_kernel<<<16, RBLK>>>(C, out);
    }
}

// round 9
// speedup vs baseline: 1.2407x; 1.0615x over previous
#include <cuda_runtime.h>
#include <math_constants.h>

#define D        256
#define NBLK     592          // flash grid: 4 CTAs per SM
#define THREADS  256
#define WARPS    (THREADS / 32)
#define NW       (NBLK * WARPS)     // 4736 warps
#define NSLOTS   100000
#define RBLK     512
#define SPLIT    65536        // slots [0,SPLIT): pin in L2; rest: stream

// ---- device scratch (no allocations allowed) ----
__device__ __align__(16) float g_u0[D];
__device__ __align__(16) float g_v[D];
__device__ __align__(16) float g_m[D];
__device__ __align__(16) float g_msum[D];
__device__ __align__(16) float g_G[D * D];         // TRANSPOSED: G_T[t][k]
__device__ float g_pmax[NBLK];
__device__ float g_psum[NBLK];
__device__ __align__(16) float g_pacc[D * NBLK];   // [dim][cta]

__device__ __forceinline__ float warp_sum(float d) {
#pragma unroll
    for (int m = 16; m >= 1; m >>= 1) d += __shfl_xor_sync(0xffffffffu, d, m);
    return d;
}
__device__ __forceinline__ float warp_max(float d) {
#pragma unroll
    for (int m = 16; m >= 1; m >>= 1) d = fmaxf(d, __shfl_xor_sync(0xffffffffu, d, m));
    return d;
}
// 256-thread block sum (8 warps)
__device__ __forceinline__ float block_sum256(float v, float* s8) {
    const int warp = threadIdx.x >> 5, lane = threadIdx.x & 31;
    v = warp_sum(v);
    if (lane == 0) s8[warp] = v;
    __syncthreads();
    float r = 0.f;
    if (warp == 0) {
        r = (lane < 8) ? s8[lane] : 0.f;
        r = warp_sum(r);
    }
    return r;   // valid in warp 0
}

// 32B loads, L2 policy variants (sm_103: evict hints require v8.b32 width)
__device__ __forceinline__ void ldg_last8(const void* p, float4& a, float4& b) {
    unsigned r0, r1, r2, r3, r4, r5, r6, r7;
    asm("ld.global.nc.L2::evict_last.v8.b32 {%0,%1,%2,%3,%4,%5,%6,%7}, [%8];"
        : "=r"(r0), "=r"(r1), "=r"(r2), "=r"(r3),
          "=r"(r4), "=r"(r5), "=r"(r6), "=r"(r7) : "l"(p));
    a.x = __uint_as_float(r0); a.y = __uint_as_float(r1);
    a.z = __uint_as_float(r2); a.w = __uint_as_float(r3);
    b.x = __uint_as_float(r4); b.y = __uint_as_float(r5);
    b.z = __uint_as_float(r6); b.w = __uint_as_float(r7);
}
__device__ __forceinline__ void ldg_first8(const void* p, float4& a, float4& b) {
    unsigned r0, r1, r2, r3, r4, r5, r6, r7;
    asm("ld.global.nc.L2::evict_first.v8.b32 {%0,%1,%2,%3,%4,%5,%6,%7}, [%8];"
        : "=r"(r0), "=r"(r1), "=r"(r2), "=r"(r3),
          "=r"(r4), "=r"(r5), "=r"(r6), "=r"(r7) : "l"(p));
    a.x = __uint_as_float(r0); a.y = __uint_as_float(r1);
    a.z = __uint_as_float(r2); a.w = __uint_as_float(r3);
    b.x = __uint_as_float(r4); b.y = __uint_as_float(r5);
    b.z = __uint_as_float(r6); b.w = __uint_as_float(r7);
}
__device__ __forceinline__ void load_slot(const char* base, int slot, int loff,
                                          float4& a, float4& b) {
    const void* p = base + (size_t)slot * 1024 + loff;
    if (slot < SPLIT) ldg_last8(p, a, b);   // warp-uniform branch
    else              ldg_first8(p, a, b);
}

// ---- setup: CTAs 0..63 -> G_T (4 columns each); CTA 64 -> u0, v0 ---------
__global__ void __launch_bounds__(256, 4)
setup_kernel(const float* __restrict__ A, const float* __restrict__ B,
             const float* __restrict__ C, const float* __restrict__ q) {
    const int t = threadIdx.x;
    if (blockIdx.x < 64) {
        // G_T[t0+i][k] = sum_d A[d][k] * C[d][t0+i]
        __shared__ float colC[4][D];
        const int t0 = blockIdx.x * 4;
        // stage 4 columns of C (each thread: 4 contiguous floats of its row)
        {
            const float* cr = C + t * D + t0;
            colC[0][t] = cr[0]; colC[1][t] = cr[1];
            colC[2][t] = cr[2]; colC[3][t] = cr[3];
        }
        __syncthreads();
        float a0 = 0.f, a1 = 0.f, a2 = 0.f, a3 = 0.f;
#pragma unroll 4
        for (int dd = 0; dd < D; dd++) {
            float a = A[dd * D + t];             // coalesced over t(=k)
            a0 = fmaf(a, colC[0][dd], a0);
            a1 = fmaf(a, colC[1][dd], a1);
            a2 = fmaf(a, colC[2][dd], a2);
            a3 = fmaf(a, colC[3][dd], a3);
        }
        g_G[(t0 + 0) * D + t] = a0;
        g_G[(t0 + 1) * D + t] = a1;
        g_G[(t0 + 2) * D + t] = a2;
        g_G[(t0 + 3) * D + t] = a3;
    } else {
        __shared__ float qs[D];
        __shared__ float us[D];
        const int warp = t >> 5, lane = t & 31;
        qs[t] = q[t];
        __syncthreads();
        for (int row = warp; row < D; row += 8) {
            const float4* r = reinterpret_cast<const float4*>(B + row * D);
            float4 c0 = r[lane * 2], c1 = r[lane * 2 + 1];
            float d = c0.x * qs[lane * 8 + 0] + c0.y * qs[lane * 8 + 1]
                    + c0.z * qs[lane * 8 + 2] + c0.w * qs[lane * 8 + 3]
                    + c1.x * qs[lane * 8 + 4] + c1.y * qs[lane * 8 + 5]
                    + c1.z * qs[lane * 8 + 6] + c1.w * qs[lane * 8 + 7];
            d = warp_sum(d);
            if (lane == 0) { us[row] = d; g_u0[row] = d; }
        }
        __syncthreads();
        float v = 0.f;
#pragma unroll 8
        for (int j = 0; j < D; j++) v = fmaf(A[j * D + t], us[j], v);
        g_v[t] = v;
    }
}

// ---------------- flash pass: fused score+softmax+weighted-sum ------------
__global__ void __launch_bounds__(THREADS, 4)
flash_kernel(const float* __restrict__ memory) {
    const int lane = threadIdx.x & 31;
    const int warp = threadIdx.x >> 5;
    const int gw   = blockIdx.x * WARPS + warp;

    float4 v0 = *reinterpret_cast<const float4*>(g_v + lane * 8);
    float4 v1 = *reinterpret_cast<const float4*>(g_v + lane * 8 + 4);

    float mx = -CUDART_INF_F, sm = 0.f;
    float acc[8];
#pragma unroll
    for (int i = 0; i < 8; i++) acc[i] = 0.f;

    const char* base = reinterpret_cast<const char*>(memory);
    const int loff = lane * 32;
    int s0 = gw;
    while (s0 + NW < NSLOTS) {
        float4 a1, b1, a2, b2;
        load_slot(base, s0, loff, a1, b1);
        load_slot(base, s0 + NW, loff, a2, b2);

        float d1 = a1.x * v0.x;     float d2 = a2.x * v0.x;
        d1 = fmaf(a1.y, v0.y, d1);  d2 = fmaf(a2.y, v0.y, d2);
        d1 = fmaf(a1.z, v0.z, d1);  d2 = fmaf(a2.z, v0.z, d2);
        d1 = fmaf(a1.w, v0.w, d1);  d2 = fmaf(a2.w, v0.w, d2);
        d1 = fmaf(b1.x, v1.x, d1);  d2 = fmaf(b2.x, v1.x, d2);
        d1 = fmaf(b1.y, v1.y, d1);  d2 = fmaf(b2.y, v1.y, d2);
        d1 = fmaf(b1.z, v1.z, d1);  d2 = fmaf(b2.z, v1.z, d2);
        d1 = fmaf(b1.w, v1.w, d1);  d2 = fmaf(b2.w, v1.w, d2);
#pragma unroll
        for (int m = 16; m >= 1; m >>= 1) {
            d1 += __shfl_xor_sync(0xffffffffu, d1, m);
            d2 += __shfl_xor_sync(0xffffffffu, d2, m);
        }
        float dmax = fmaxf(d1, d2);
        if (dmax > mx) {                       // warp-uniform branch
            float scale = __expf(mx - dmax);
            mx = dmax; sm *= scale;
#pragma unroll
            for (int i = 0; i < 8; i++) acc[i] *= scale;
        }
        float w1 = __expf(d1 - mx);
        float w2 = __expf(d2 - mx);
        sm += w1 + w2;
        acc[0] = fmaf(w1, a1.x, fmaf(w2, a2.x, acc[0]));
        acc[1] = fmaf(w1, a1.y, fmaf(w2, a2.y, acc[1]));
        acc[2] = fmaf(w1, a1.z, fmaf(w2, a2.z, acc[2]));
        acc[3] = fmaf(w1, a1.w, fmaf(w2, a2.w, acc[3]));
        acc[4] = fmaf(w1, b1.x, fmaf(w2, b2.x, acc[4]));
        acc[5] = fmaf(w1, b1.y, fmaf(w2, b2.y, acc[5]));
        acc[6] = fmaf(w1, b1.z, fmaf(w2, b2.z, acc[6]));
        acc[7] = fmaf(w1, b1.w, fmaf(w2, b2.w, acc[7]));
        s0 += 2 * NW;
    }
    if (s0 < NSLOTS) {
        float4 a1, b1;
        load_slot(base, s0, loff, a1, b1);
        float d = a1.x * v0.x;
        d = fmaf(a1.y, v0.y, d); d = fmaf(a1.z, v0.z, d); d = fmaf(a1.w, v0.w, d);
        d = fmaf(b1.x, v1.x, d); d = fmaf(b1.y, v1.y, d);
        d = fmaf(b1.z, v1.z, d); d = fmaf(b1.w, v1.w, d);
        d = warp_sum(d);
        if (d > mx) {
            float scale = __expf(mx - d);
            mx = d; sm *= scale;
#pragma unroll
            for (int i = 0; i < 8; i++) acc[i] *= scale;
        }
        float w = __expf(d - mx);
        sm += w;
        acc[0] = fmaf(w, a1.x, acc[0]); acc[1] = fmaf(w, a1.y, acc[1]);
        acc[2] = fmaf(w, a1.z, acc[2]); acc[3] = fmaf(w, a1.w, acc[3]);
        acc[4] = fmaf(w, b1.x, acc[4]); acc[5] = fmaf(w, b1.y, acc[5]);
        acc[6] = fmaf(w, b1.z, acc[6]); acc[7] = fmaf(w, b1.w, acc[7]);
    }

    __shared__ float s_mx[WARPS], s_sm[WARPS];
    __shared__ float s_acc[WARPS][D];
    if (lane == 0) { s_mx[warp] = mx; s_sm[warp] = sm; }
#pragma unroll
    for (int i = 0; i < 8; i++) s_acc[warp][lane * 8 + i] = acc[i];
    __syncthreads();

    const int t = threadIdx.x;
    float M = s_mx[0];
#pragma unroll
    for (int w = 1; w < WARPS; w++) M = fmaxf(M, s_mx[w]);
    float tot = 0.f;
#pragma unroll
    for (int w = 0; w < WARPS; w++) tot = fmaf(s_acc[w][t], __expf(s_mx[w] - M), tot);
    g_pacc[t * NBLK + blockIdx.x] = tot;       // transposed for reduce
    if (t == 0) {
        float S = 0.f;
#pragma unroll
        for (int w = 0; w < WARPS; w++) S = fmaf(s_sm[w], __expf(s_mx[w] - M), S);
        g_psum[blockIdx.x] = S;
        g_pmax[blockIdx.x] = M;
    }
}

// ---------------- distributed reduce: CTA j -> m[j]  (shfl-based) ---------
__global__ void __launch_bounds__(RBLK, 2)
reduce_kernel(int hop) {
    __shared__ float s1[16], s2[16];
    __shared__ float sM;
    const int j = blockIdx.x, t = threadIdx.x;
    const int warp = t >> 5, lane = t & 31;

    const bool v0ok = (t < NBLK), v1ok = (t + RBLK < NBLK);
    float pm0 = v0ok ? g_pmax[t] : -CUDART_INF_F;
    float pm1 = v1ok ? g_pmax[t + RBLK] : -CUDART_INF_F;
    float ps0 = v0ok ? g_psum[t] : 0.f;
    float ps1 = v1ok ? g_psum[t + RBLK] : 0.f;
    float pa0 = v0ok ? g_pacc[j * NBLK + t] : 0.f;
    float pa1 = v1ok ? g_pacc[j * NBLK + t + RBLK] : 0.f;

    float mx = warp_max(fmaxf(pm0, pm1));
    if (lane == 0) s1[warp] = mx;
    __syncthreads();
    if (warp == 0) {
        float v = (lane < 16) ? s1[lane] : -CUDART_INF_F;
        v = warp_max(v);
        if (lane == 0) sM = v;
    }
    __syncthreads();
    const float M = sM;

    float w0 = v0ok ? __expf(pm0 - M) : 0.f;
    float w1 = v1ok ? __expf(pm1 - M) : 0.f;
    float ss = fmaf(w0, ps0, w1 * ps1);
    float pa = fmaf(w0, pa0, w1 * pa1);
#pragma unroll
    for (int m = 16; m >= 1; m >>= 1) {
        ss += __shfl_xor_sync(0xffffffffu, ss, m);
        pa += __shfl_xor_sync(0xffffffffu, pa, m);
    }
    if (lane == 0) { s1[warp] = ss; s2[warp] = pa; }
    __syncthreads();
    if (warp == 0) {
        float a = (lane < 16) ? s1[lane] : 0.f;
        float b = (lane < 16) ? s2[lane] : 0.f;
#pragma unroll
        for (int m = 16; m >= 1; m >>= 1) {
            a += __shfl_xor_sync(0xffffffffu, a, m);
            b += __shfl_xor_sync(0xffffffffu, b, m);
        }
        if (lane == 0) {
            float mj = b / a;
            g_m[j] = mj;
            g_msum[j] = (hop == 0) ? mj : g_msum[j] + mj;
        }
    }
}

// -------- v[j] += G_T[j,:].m   (CTA per output element, block reduce) ------
__global__ void __launch_bounds__(256, 4)
vupd_kernel() {
    __shared__ float s8[8];
    const int j = blockIdx.x, t = threadIdx.x;
    float p = g_G[j * D + t] * g_m[t];
    float r = block_sum256(p, s8);
    if (t == 0) g_v[j] += r;
}

// -------- out[j] = u0[j] + C[j,:].msum  (CTA per output element) -----------
__global__ void __launch_bounds__(256, 4)
final_kernel(const float* __restrict__ C, float* __restrict__ out) {
    __shared__ float s8[8];
    const int j = blockIdx.x, t = threadIdx.x;
    float p = C[j * D + t] * g_msum[t];
    float r = block_sum256(p, s8);
    if (t == 0) out[j] = g_u0[j] + r;
}

extern "C" void kernel_launch(void* const* d_in, const int* in_sizes, int n_in,
                              void* d_out, int out_size) {
    const float* memory = (const float*)d_in[0];
    const float* query  = (const float*)d_in[1];
    const float* A      = (const float*)d_in[2];
    const float* B      = (const float*)d_in[3];
    const float* C      = (const float*)d_in[4];
    float* out = (float*)d_out;

    setup_kernel<<<65, 256>>>(A, B, C, query);
    for (int h = 0; h < 3; h++) {
        flash_kernel<<<NBLK, THREADS>>>(memory);
        reduce_kernel<<<256, RBLK>>>(h);
        if (h < 2) vupd_kernel<<<256, 256>>>();
        else       final_kernel<<<256, 256>>>(C, out);
    }
}